// round 3
// baseline (speedup 1.0000x reference)
#include <cuda_runtime.h>
#include <math.h>
#include <stdint.h>

#define BB 16
#define LSEQ 1024
#define EE 128
#define OO 256
#define HH 256
#define CC 768
#define ZC 3840
#define KK 11

// ---------- static device scratch ----------
__device__ __align__(16) float g_P0[(size_t)BB*OO*LSEQ];
__device__ __align__(16) float g_P1[(size_t)BB*OO*LSEQ];
__device__ __align__(16) float g_Wb[(size_t)BB*OO*OO*KK];
__device__ float g_pooled[BB*OO];
__device__ float g_rbuf[BB*4];
__device__ __align__(16) float g_Z[(size_t)BB*ZC*LSEQ];     // [B,3840,L]
__device__ __align__(16) float g_G[(size_t)2*BB*LSEQ*1024]; // LSTM pre-gates
__device__ __align__(16) float g_WT[2*1024*HH];             // Whh^T per dir: [e][row]

__device__ __forceinline__ float sigf(float x){ return 1.f/(1.f+expf(-x)); }

// ---------- row sums for routing pool ----------
__global__ void pool_kernel(const float* __restrict__ x){
  const float* row = x + (size_t)blockIdx.x * LSEQ;
  float s = 0.f;
  for (int t = threadIdx.x; t < LSEQ; t += 256) s += row[t];
  __shared__ float red[256];
  red[threadIdx.x] = s; __syncthreads();
  for (int off = 128; off; off >>= 1){
    if (threadIdx.x < off) red[threadIdx.x] += red[threadIdx.x+off];
    __syncthreads();
  }
  if (threadIdx.x == 0) g_pooled[blockIdx.x] = red[0];
}

// ---------- routing r = sigmoid(mean @ rw.T + rb), mean over padded len ----------
__global__ void routing_kernel(const float* __restrict__ rw, const float* __restrict__ rb, int I){
  int b = threadIdx.x;
  if (b >= BB) return;
  const float inv = 1.f / (float)(LSEQ + KK - 1);
  // pooled rows for sample b start at b*I in g_pooled (pool grid was B*I)
  float rs = 0.f;
  for (int e = 0; e < 3; e++){
    float acc = rb[e];
    for (int i = 0; i < I; i++) acc = fmaf(g_pooled[b*I + i]*inv, rw[e*I+i], acc);
    float r = sigf(acc);
    g_rbuf[b*4+e] = r; rs += r;
  }
  g_rbuf[b*4+3] = rs;
}

// ---------- Wb[b] = sum_e r[b,e] * W[e] ----------
__global__ void wbuild_kernel(const float* __restrict__ W, int I){
  int per4 = (OO*I*KK) >> 2;
  int idx = blockIdx.x*256 + threadIdx.x;
  if (idx >= BB*per4) return;
  int b = idx / per4, m = idx - b*per4;
  const float4* w = (const float4*)W;
  float r0 = g_rbuf[b*4+0], r1 = g_rbuf[b*4+1], r2 = g_rbuf[b*4+2];
  float4 a = w[m], c = w[per4+m], d = w[2*per4+m];
  float4 o;
  o.x = r0*a.x + r1*c.x + r2*d.x;
  o.y = r0*a.y + r1*c.y + r2*d.y;
  o.z = r0*a.z + r1*c.z + r2*d.z;
  o.w = r0*a.w + r1*c.w + r2*d.w;
  ((float4*)g_Wb)[(size_t)b*per4 + m] = o;
}

// ---------- fused gated causal conv layer ----------
// out[b,o,t] = (convWb + rsum*condb[o] + lbias[o]) * sigmoid(convWg + gateb[o] + lc[o]) [+ res]
__global__ void __launch_bounds__(256) gated_conv_kernel(
  const float* __restrict__ x, int I, long in_bs,
  float* __restrict__ out, long out_bs,
  const float* __restrict__ res,
  const float* __restrict__ Wg, const float* __restrict__ condb,
  const float* __restrict__ lbias, const float* __restrict__ gateb,
  const float* __restrict__ lc)
{
  const int t0 = blockIdx.x*64, o0 = blockIdx.y*64, b = blockIdx.z;
  __shared__ float xs[8][76];          // t range [t0-10, t0+63]
  __shared__ float wa[8*64*11];        // layout [(o*8+i)*11+k]
  __shared__ float wg[8*64*11];
  const int tid = threadIdx.x, tt = tid & 15, to = tid >> 4;
  float accA[4][4] = {}, accG[4][4] = {};
  const float* wbB = g_Wb + (size_t)b*OO*I*KK;

  for (int cb = 0; cb < I; cb += 8){
    __syncthreads();
    for (int idx = tid; idx < 8*74; idx += 256){
      int i = idx/74, j = idx - i*74;
      int tg = t0 - 10 + j;
      xs[i][j] = (tg >= 0) ? x[(size_t)b*in_bs + (size_t)(cb+i)*LSEQ + tg] : 0.f;
    }
    for (int idx = tid; idx < 8*64*11; idx += 256){
      int o = idx/88, r = idx - o*88;       // r = i*11+k, contiguous in global
      int gidx = ((o0+o)*I + cb)*KK + r;
      wa[idx] = wbB[gidx];
      wg[idx] = Wg[gidx];
    }
    __syncthreads();
    #pragma unroll
    for (int i = 0; i < 8; i++){
      float xr[14];
      #pragma unroll
      for (int j = 0; j < 14; j++) xr[j] = xs[i][tt*4 + j];
      #pragma unroll
      for (int oj = 0; oj < 4; oj++){
        const float* wAp = &wa[((to*4+oj)*8 + i)*11];
        const float* wGp = &wg[((to*4+oj)*8 + i)*11];
        #pragma unroll
        for (int k = 0; k < 11; k++){
          float wA = wAp[k], wGv = wGp[k];
          #pragma unroll
          for (int j = 0; j < 4; j++){
            accA[oj][j] = fmaf(xr[k+j], wA,  accA[oj][j]);
            accG[oj][j] = fmaf(xr[k+j], wGv, accG[oj][j]);
          }
        }
      }
    }
  }
  float rsum = g_rbuf[b*4+3];
  #pragma unroll
  for (int oj = 0; oj < 4; oj++){
    int o = o0 + to*4 + oj;
    float cA = rsum*condb[o] + lbias[o];
    float cG = gateb[o] + lc[o];
    #pragma unroll
    for (int j = 0; j < 4; j++){
      int t = t0 + tt*4 + j;
      float v = (accA[oj][j] + cA) * sigf(accG[oj][j] + cG);
      if (res) v += res[(size_t)b*(OO*LSEQ) + (size_t)o*LSEQ + t];
      out[(size_t)b*out_bs + (size_t)o*LSEQ + t] = v;
    }
  }
}

// ---------- LSTM pre-gates: G[dir,b,t,g] = seq[b,:,t] @ Wih^T + bih + bhh ----------
__global__ void __launch_bounds__(256) lstm_pregemm_kernel(
  const float* __restrict__ seq, const float* __restrict__ wih,
  const float* __restrict__ bih, const float* __restrict__ bhh)
{
  const int t0 = blockIdx.x*64, g0 = blockIdx.y*64;
  const int blk = blockIdx.z, dir = blk >> 4, b = blk & 15;
  __shared__ float xs[16][64];
  __shared__ float ws[64][17];
  const int tid = threadIdx.x, tt = tid & 15, tg = tid >> 4; // tt->g fast, tg->t
  float acc[4][4] = {};                                       // [gj][j(t)]
  const float* W = wih + (size_t)dir*1024*EE;
  for (int e0 = 0; e0 < EE; e0 += 16){
    __syncthreads();
    for (int idx = tid; idx < 16*64; idx += 256){
      int e = idx >> 6, t = idx & 63;
      xs[e][t] = seq[((size_t)b*EE + e0+e)*LSEQ + t0+t];
    }
    for (int idx = tid; idx < 64*16; idx += 256){
      int g = idx >> 4, e = idx & 15;
      ws[g][e] = W[(size_t)(g0+g)*EE + e0+e];
    }
    __syncthreads();
    #pragma unroll
    for (int e = 0; e < 16; e++){
      float wv[4];
      #pragma unroll
      for (int gj = 0; gj < 4; gj++) wv[gj] = ws[tt*4+gj][e];
      #pragma unroll
      for (int j = 0; j < 4; j++){
        float xv = xs[e][tg*4+j];
        #pragma unroll
        for (int gj = 0; gj < 4; gj++) acc[gj][j] = fmaf(xv, wv[gj], acc[gj][j]);
      }
    }
  }
  #pragma unroll
  for (int j = 0; j < 4; j++){
    int t = t0 + tg*4 + j;
    size_t base = (((size_t)blk << 10) + t) << 10;
    #pragma unroll
    for (int gj = 0; gj < 4; gj++){
      int g = g0 + tt*4 + gj;
      g_G[base + g] = acc[gj][j] + bih[dir*1024+g] + bhh[dir*1024+g];
    }
  }
}

__global__ void whhT_kernel(const float* __restrict__ whh){
  int idx = blockIdx.x*256 + threadIdx.x;      // 2*1024*256
  int dir = idx >> 18, rem = idx & 262143;
  int row = rem >> 8, e = rem & 255;
  g_WT[dir*262144 + e*1024 + row] = whh[idx];
}

// ---------- sequential LSTM recurrence, one block per (dir,b) ----------
__global__ void __launch_bounds__(256) lstm_step_kernel(){
  const int blk = blockIdx.x, dir = blk >> 4, b = blk & 15, j = threadIdx.x;
  __shared__ float hs[256];
  hs[j] = 0.f;
  float c = 0.f;
  const float* WT = g_WT + dir*262144;
  __syncthreads();
  for (int s = 0; s < 1024; s++){
    int t = dir ? (1023 - s) : s;
    const float* gp = g_G + ((((size_t)blk << 10) + t) << 10);
    float a0 = gp[j], a1 = gp[256+j], a2 = gp[512+j], a3 = gp[768+j];
    #pragma unroll 4
    for (int e = 0; e < 256; e++){
      float hv = hs[e];
      const float* w = WT + e*1024 + j;
      a0 = fmaf(hv, w[0],   a0);
      a1 = fmaf(hv, w[256], a1);
      a2 = fmaf(hv, w[512], a2);
      a3 = fmaf(hv, w[768], a3);
    }
    c = sigf(a1)*c + sigf(a0)*tanhf(a2);
    float hh = sigf(a3)*tanhf(c);
    __syncthreads();
    hs[j] = hh;
    __syncthreads();
    g_Z[((size_t)b*ZC + 256 + dir*256 + j)*LSEQ + t] = hh;
  }
}

// ---------- ASPP branch: relu(conv3 dil d)+BN into g_Z chunk ----------
__global__ void __launch_bounds__(256) aspp_kernel(
  const float* __restrict__ w, const float* __restrict__ bias,
  const float* __restrict__ bng, const float* __restrict__ bnb,
  int d, int outbase)
{
  const int t0 = blockIdx.x*64, c0 = blockIdx.y*64, b = blockIdx.z;
  __shared__ float xs[8][80];          // t range [t0-8, t0+71]
  __shared__ float ws[8*64*3];         // [(c*8+i)*3+k]
  const int tid = threadIdx.x, tt = tid & 15, tc = tid >> 4;
  float acc[4][4] = {};
  for (int cb = 0; cb < CC; cb += 8){
    __syncthreads();
    for (int idx = tid; idx < 8*80; idx += 256){
      int i = idx/80, jj = idx - i*80;
      int gx = t0 - 8 + jj;
      xs[i][jj] = (gx >= 0 && gx < LSEQ) ? g_Z[((size_t)b*ZC + cb+i)*LSEQ + gx] : 0.f;
    }
    for (int idx = tid; idx < 64*8*3; idx += 256){
      int cch = idx/24, r = idx - cch*24;   // r = i*3+k contiguous in global
      ws[idx] = w[((size_t)(c0+cch)*CC + cb)*3 + r];
    }
    __syncthreads();
    #pragma unroll
    for (int i = 0; i < 8; i++){
      float x0[4], x1[4], x2[4];
      #pragma unroll
      for (int j = 0; j < 4; j++){
        int base = tt*4 + j + 8;
        x0[j] = xs[i][base-d]; x1[j] = xs[i][base]; x2[j] = xs[i][base+d];
      }
      #pragma unroll
      for (int cj = 0; cj < 4; cj++){
        const float* wp = &ws[((tc*4+cj)*8 + i)*3];
        float w0 = wp[0], w1 = wp[1], w2 = wp[2];
        #pragma unroll
        for (int j = 0; j < 4; j++)
          acc[cj][j] = fmaf(x0[j], w0, fmaf(x1[j], w1, fmaf(x2[j], w2, acc[cj][j])));
      }
    }
  }
  const float inv = rsqrtf(1.f + 1e-5f);
  #pragma unroll
  for (int cj = 0; cj < 4; cj++){
    int cch = c0 + tc*4 + cj;
    float bg = inv*bng[cch], bbv = bnb[cch], bi = bias[cch];
    #pragma unroll
    for (int j = 0; j < 4; j++){
      int t = t0 + tt*4 + j;
      float v = fmaxf(acc[cj][j] + bi, 0.f);
      g_Z[((size_t)b*ZC + outbase + cch)*LSEQ + t] = v*bg + bbv;
    }
  }
}

// ---------- 1x1 head + log-sigmoid ----------
__global__ void __launch_bounds__(256) head_kernel(
  const float* __restrict__ w1, const float* __restrict__ b1, float* __restrict__ out)
{
  const int blk = blockIdx.x, b = blk >> 4, t0 = (blk & 15)*64;
  const int ct = threadIdx.x >> 6, tl = threadIdx.x & 63;
  const int t = t0 + tl;
  float acc[9] = {};
  const float* zp = g_Z + (size_t)b*ZC*LSEQ + t;
  for (int c = ct*960; c < ct*960 + 960; c++){
    float zv = zp[(size_t)c*LSEQ];
    #pragma unroll
    for (int cls = 0; cls < 9; cls++) acc[cls] = fmaf(zv, w1[cls*ZC + c], acc[cls]);
  }
  __shared__ float red[4][64][9];
  #pragma unroll
  for (int cls = 0; cls < 9; cls++) red[ct][tl][cls] = acc[cls];
  __syncthreads();
  if (ct == 0){
    #pragma unroll
    for (int cls = 0; cls < 9; cls++){
      float v = red[0][tl][cls] + red[1][tl][cls] + red[2][tl][cls] + red[3][tl][cls] + b1[cls];
      float ls = (v >= 0.f) ? -log1pf(expf(-v)) : (v - log1pf(expf(v)));
      out[((size_t)b*9 + cls)*LSEQ + t] = ls;
    }
  }
}

extern "C" void kernel_launch(void* const* d_in, const int* in_sizes, int n_in,
                              void* d_out, int out_size){
  const float* seq     = (const float*)d_in[0];
  const float* cond0_w = (const float*)d_in[1];
  const float* cond0_b = (const float*)d_in[2];
  const float* rout0_w = (const float*)d_in[3];
  const float* rout0_b = (const float*)d_in[4];
  const float* b0      = (const float*)d_in[5];
  const float* gate0_w = (const float*)d_in[6];
  const float* gate0_b = (const float*)d_in[7];
  const float* c0      = (const float*)d_in[8];
  const float* cond_ws = (const float*)d_in[9];
  const float* cond_bs = (const float*)d_in[10];
  const float* rout_ws = (const float*)d_in[11];
  const float* rout_bs = (const float*)d_in[12];
  const float* bs      = (const float*)d_in[13];
  const float* gate_ws = (const float*)d_in[14];
  const float* gate_bs = (const float*)d_in[15];
  const float* cs      = (const float*)d_in[16];
  const float* lstm_wih= (const float*)d_in[17];
  const float* lstm_whh= (const float*)d_in[18];
  const float* lstm_bih= (const float*)d_in[19];
  const float* lstm_bhh= (const float*)d_in[20];
  const float* aspp_ws = (const float*)d_in[21];
  const float* aspp_bs = (const float*)d_in[22];
  const float* bn_g    = (const float*)d_in[23];
  const float* bn_b    = (const float*)d_in[24];
  const float* conv1_w = (const float*)d_in[25];
  const float* conv1_b = (const float*)d_in[26];
  float* out = (float*)d_out;

  float *P0, *P1, *Z;
  cudaGetSymbolAddress((void**)&P0, g_P0);
  cudaGetSymbolAddress((void**)&P1, g_P1);
  cudaGetSymbolAddress((void**)&Z,  g_Z);

  const long PBS = (long)OO*LSEQ;       // 262144
  const long ZBS = (long)ZC*LSEQ;       // 3932160
  dim3 gc(16, 4, 16);

  // layer 0 (I = 128, input = seq)
  pool_kernel<<<BB*EE, 256>>>(seq);
  routing_kernel<<<1, 16>>>(rout0_w, rout0_b, EE);
  wbuild_kernel<<<(BB*((OO*EE*KK)/4) + 255)/256, 256>>>(cond0_w, EE);
  gated_conv_kernel<<<gc, 256>>>(seq, EE, (long)EE*LSEQ, P0, PBS, (const float*)0,
                                 gate0_w, cond0_b, b0, gate0_b, c0);

  // stacked layers (I = 256)
  const size_t WSTRIDE = (size_t)3*OO*OO*KK;   // cond_ws per-layer stride
  const size_t GSTRIDE = (size_t)OO*OO*KK;     // gate_ws per-layer stride
  const float* inb[4]  = { P0, P1, P0, P1 };
  float*       outb[4] = { P1, P0, P1, Z  };
  const float* resb[4] = { P0, 0,  P1, 0  };   // i%2==0 -> add res
  const long   obs[4]  = { PBS, PBS, PBS, ZBS };
  for (int i = 0; i < 4; i++){
    pool_kernel<<<BB*OO, 256>>>(inb[i]);
    routing_kernel<<<1, 16>>>(rout_ws + i*3*OO, rout_bs + i*3, OO);
    wbuild_kernel<<<(BB*((OO*OO*KK)/4) + 255)/256, 256>>>(cond_ws + i*WSTRIDE, OO);
    gated_conv_kernel<<<gc, 256>>>(inb[i], OO, PBS, outb[i], obs[i], resb[i],
                                   gate_ws + i*GSTRIDE, cond_bs + i*OO, bs + i*OO,
                                   gate_bs + i*OO, cs + i*OO);
  }

  // biLSTM
  dim3 gp(16, 16, 32);
  lstm_pregemm_kernel<<<gp, 256>>>(seq, lstm_wih, lstm_bih, lstm_bhh);
  whhT_kernel<<<2048, 256>>>(lstm_whh);
  lstm_step_kernel<<<32, 256>>>();

  // ASPP branches into g_Z chunks 1..4
  dim3 ga(16, 12, 16);
  const int dils[4] = {1, 2, 4, 8};
  for (int j = 0; j < 4; j++)
    aspp_kernel<<<ga, 256>>>(aspp_ws + (size_t)j*CC*CC*3, aspp_bs + j*CC,
                             bn_g + j*CC, bn_b + j*CC, dils[j], CC*(1+j));

  // head
  head_kernel<<<256, 256>>>(conv1_w, conv1_b, out);
}

// round 4
// speedup vs baseline: 1.5259x; 1.5259x over previous
#include <cuda_runtime.h>
#include <math.h>
#include <stdint.h>

#define BB 16
#define LSEQ 1024
#define EE 128
#define OO 256
#define HH 256
#define CC 768
#define ZC 3840
#define KK 11

typedef unsigned long long u64;

// ---------- static device scratch ----------
__device__ __align__(16) float g_P0[(size_t)BB*OO*LSEQ];
__device__ __align__(16) float g_P1[(size_t)BB*OO*LSEQ];
__device__ __align__(16) float g_Wb[(size_t)BB*OO*OO*KK];
__device__ float g_pooled[BB*OO];
__device__ float g_rbuf[BB*4];
__device__ __align__(16) float g_Z[(size_t)BB*ZC*LSEQ];     // [B,3840,L]
__device__ __align__(16) float g_G[(size_t)2*BB*LSEQ*1024]; // LSTM pre-gates
__device__ __align__(16) float g_WT[2*1024*HH];             // Whh^T per dir: [e][row]

__device__ __forceinline__ float sigf(float x){ return 1.f/(1.f+expf(-x)); }

__device__ __forceinline__ u64 pk2(float lo, float hi){
  u64 r; asm("mov.b64 %0, {%1, %2};" : "=l"(r) : "f"(lo), "f"(hi)); return r;
}
__device__ __forceinline__ void fma2(u64 &d, u64 a, u64 b){
  asm("fma.rn.f32x2 %0, %1, %2, %0;" : "+l"(d) : "l"(a), "l"(b));
}
__device__ __forceinline__ float2 up2(u64 v){
  float2 f; asm("mov.b64 {%0, %1}, %2;" : "=f"(f.x), "=f"(f.y) : "l"(v)); return f;
}

// ---------- row sums for routing pool ----------
__global__ void pool_kernel(const float* __restrict__ x){
  const float* row = x + (size_t)blockIdx.x * LSEQ;
  float s = 0.f;
  for (int t = threadIdx.x; t < LSEQ; t += 256) s += row[t];
  __shared__ float red[256];
  red[threadIdx.x] = s; __syncthreads();
  for (int off = 128; off; off >>= 1){
    if (threadIdx.x < off) red[threadIdx.x] += red[threadIdx.x+off];
    __syncthreads();
  }
  if (threadIdx.x == 0) g_pooled[blockIdx.x] = red[0];
}

// ---------- routing r = sigmoid(mean @ rw.T + rb), mean over padded len ----------
__global__ void routing_kernel(const float* __restrict__ rw, const float* __restrict__ rb, int I){
  int b = threadIdx.x;
  if (b >= BB) return;
  const float inv = 1.f / (float)(LSEQ + KK - 1);
  float rs = 0.f;
  for (int e = 0; e < 3; e++){
    float acc = rb[e];
    for (int i = 0; i < I; i++) acc = fmaf(g_pooled[b*I + i]*inv, rw[e*I+i], acc);
    float r = sigf(acc);
    g_rbuf[b*4+e] = r; rs += r;
  }
  g_rbuf[b*4+3] = rs;
}

// ---------- Wb[b] = sum_e r[b,e] * W[e] ----------
__global__ void wbuild_kernel(const float* __restrict__ W, int I){
  int per4 = (OO*I*KK) >> 2;
  int idx = blockIdx.x*256 + threadIdx.x;
  if (idx >= BB*per4) return;
  int b = idx / per4, m = idx - b*per4;
  const float4* w = (const float4*)W;
  float r0 = g_rbuf[b*4+0], r1 = g_rbuf[b*4+1], r2 = g_rbuf[b*4+2];
  float4 a = w[m], c = w[per4+m], d = w[2*per4+m];
  float4 o;
  o.x = r0*a.x + r1*c.x + r2*d.x;
  o.y = r0*a.y + r1*c.y + r2*d.y;
  o.z = r0*a.z + r1*c.z + r2*d.z;
  o.w = r0*a.w + r1*c.w + r2*d.w;
  ((float4*)g_Wb)[(size_t)b*per4 + m] = o;
}

// ---------- fused gated causal conv layer (f32x2 packed over output-channel pairs) ----------
__global__ void __launch_bounds__(256) gated_conv_kernel(
  const float* __restrict__ x, int I, long in_bs,
  float* __restrict__ out, long out_bs,
  const float* __restrict__ res,
  const float* __restrict__ Wg, const float* __restrict__ condb,
  const float* __restrict__ lbias, const float* __restrict__ gateb,
  const float* __restrict__ lc)
{
  const int t0 = blockIdx.x*64, o0 = blockIdx.y*64, b = blockIdx.z;
  __shared__ float xs[8][76];          // t range [t0-10, t0+63]
  __shared__ float wa2[88*66];         // [r = i*11+k][o], padded row 66
  __shared__ float wg2[88*66];
  const int tid = threadIdx.x, tt = tid & 15, to = tid >> 4;
  u64 accA[2][4] = {}, accG[2][4] = {};
  const float* wbB = g_Wb + (size_t)b*OO*I*KK;

  for (int cb = 0; cb < I; cb += 8){
    __syncthreads();
    for (int idx = tid; idx < 8*74; idx += 256){
      int i = idx/74, j = idx - i*74;
      int tg = t0 - 10 + j;
      xs[i][j] = (tg >= 0) ? x[(size_t)b*in_bs + (size_t)(cb+i)*LSEQ + tg] : 0.f;
    }
    for (int idx = tid; idx < 88*64; idx += 256){
      int o = idx/88, r = idx - o*88;       // r = i*11+k, contiguous in global
      int gidx = ((o0+o)*I + cb)*KK + r;
      wa2[r*66 + o] = wbB[gidx];
      wg2[r*66 + o] = Wg[gidx];
    }
    __syncthreads();
    #pragma unroll
    for (int i = 0; i < 8; i++){
      u64 xb[14];
      #pragma unroll
      for (int m = 0; m < 14; m++){
        float xv = xs[i][tt*4 + m];
        xb[m] = pk2(xv, xv);
      }
      #pragma unroll
      for (int k = 0; k < 11; k++){
        const int rr = i*11 + k;
        u64 wA0 = *(const u64*)(wa2 + rr*66 + to*4);
        u64 wA1 = *(const u64*)(wa2 + rr*66 + to*4 + 2);
        u64 wG0 = *(const u64*)(wg2 + rr*66 + to*4);
        u64 wG1 = *(const u64*)(wg2 + rr*66 + to*4 + 2);
        #pragma unroll
        for (int jj = 0; jj < 4; jj++){
          fma2(accA[0][jj], xb[k+jj], wA0);
          fma2(accA[1][jj], xb[k+jj], wA1);
          fma2(accG[0][jj], xb[k+jj], wG0);
          fma2(accG[1][jj], xb[k+jj], wG1);
        }
      }
    }
  }
  float rsum = g_rbuf[b*4+3];
  #pragma unroll
  for (int p = 0; p < 2; p++){
    int olo = o0 + to*4 + 2*p, ohi = olo + 1;
    float cAlo = rsum*condb[olo] + lbias[olo], cAhi = rsum*condb[ohi] + lbias[ohi];
    float cGlo = gateb[olo] + lc[olo],         cGhi = gateb[ohi] + lc[ohi];
    #pragma unroll
    for (int jj = 0; jj < 4; jj++){
      int t = t0 + tt*4 + jj;
      float2 vA = up2(accA[p][jj]);
      float2 vG = up2(accG[p][jj]);
      float vlo = (vA.x + cAlo) * sigf(vG.x + cGlo);
      float vhi = (vA.y + cAhi) * sigf(vG.y + cGhi);
      if (res){
        vlo += res[(size_t)b*(OO*LSEQ) + (size_t)olo*LSEQ + t];
        vhi += res[(size_t)b*(OO*LSEQ) + (size_t)ohi*LSEQ + t];
      }
      out[(size_t)b*out_bs + (size_t)olo*LSEQ + t] = vlo;
      out[(size_t)b*out_bs + (size_t)ohi*LSEQ + t] = vhi;
    }
  }
}

// ---------- LSTM pre-gates: G[dir,b,t,g] = seq[b,:,t] @ Wih^T + bih + bhh ----------
__global__ void __launch_bounds__(256) lstm_pregemm_kernel(
  const float* __restrict__ seq, const float* __restrict__ wih,
  const float* __restrict__ bih, const float* __restrict__ bhh)
{
  const int t0 = blockIdx.x*64, g0 = blockIdx.y*64;
  const int blk = blockIdx.z, dir = blk >> 4, b = blk & 15;
  __shared__ float xs[16][64];
  __shared__ float ws[64][17];
  const int tid = threadIdx.x, tt = tid & 15, tg = tid >> 4;
  float acc[4][4] = {};
  const float* W = wih + (size_t)dir*1024*EE;
  for (int e0 = 0; e0 < EE; e0 += 16){
    __syncthreads();
    for (int idx = tid; idx < 16*64; idx += 256){
      int e = idx >> 6, t = idx & 63;
      xs[e][t] = seq[((size_t)b*EE + e0+e)*LSEQ + t0+t];
    }
    for (int idx = tid; idx < 64*16; idx += 256){
      int g = idx >> 4, e = idx & 15;
      ws[g][e] = W[(size_t)(g0+g)*EE + e0+e];
    }
    __syncthreads();
    #pragma unroll
    for (int e = 0; e < 16; e++){
      float wv[4];
      #pragma unroll
      for (int gj = 0; gj < 4; gj++) wv[gj] = ws[tt*4+gj][e];
      #pragma unroll
      for (int j = 0; j < 4; j++){
        float xv = xs[e][tg*4+j];
        #pragma unroll
        for (int gj = 0; gj < 4; gj++) acc[gj][j] = fmaf(xv, wv[gj], acc[gj][j]);
      }
    }
  }
  #pragma unroll
  for (int j = 0; j < 4; j++){
    int t = t0 + tg*4 + j;
    size_t base = (((size_t)blk << 10) + t) << 10;
    #pragma unroll
    for (int gj = 0; gj < 4; gj++){
      int g = g0 + tt*4 + gj;
      g_G[base + g] = acc[gj][j] + bih[dir*1024+g] + bhh[dir*1024+g];
    }
  }
}

__global__ void whhT_kernel(const float* __restrict__ whh){
  int idx = blockIdx.x*256 + threadIdx.x;      // 2*1024*256
  int dir = idx >> 18, rem = idx & 262143;
  int row = rem >> 8, e = rem & 255;
  g_WT[dir*262144 + e*1024 + row] = whh[idx];
}

// ---------- sequential LSTM recurrence, one block per (dir,b) ----------
// thread j: gate g = j>>6, columns (j&63)*4 .. +3  -> one LDG.128 per e, packed f32x2 FMAs
__global__ void __launch_bounds__(256) lstm_step_kernel(){
  const int blk = blockIdx.x, dir = blk >> 4, b = blk & 15, j = threadIdx.x;
  __shared__ float hs[256];
  __shared__ float gsm[1024];
  __shared__ float cst[256];
  hs[j] = 0.f; cst[j] = 0.f;
  const ulonglong2* W2 = (const ulonglong2*)(g_WT + (size_t)dir*262144);
  __syncthreads();
  for (int s = 0; s < 1024; s++){
    int t = dir ? (1023 - s) : s;
    const float4* gp4 = (const float4*)(g_G + ((((size_t)blk << 10) + t) << 10));
    float4 av = gp4[j];
    u64 a01 = pk2(av.x, av.y), a23 = pk2(av.z, av.w);
    #pragma unroll 8
    for (int e = 0; e < 256; e++){
      ulonglong2 w = W2[(size_t)e*256 + j];
      float hv = hs[e];
      u64 hb = pk2(hv, hv);
      fma2(a01, hb, w.x);
      fma2(a23, hb, w.y);
    }
    *(u64*)(gsm + j*4)     = a01;
    *(u64*)(gsm + j*4 + 2) = a23;
    __syncthreads();
    float iv = gsm[j], fv = gsm[256+j], gv = gsm[512+j], ov = gsm[768+j];
    float c = sigf(fv)*cst[j] + sigf(iv)*tanhf(gv);
    float h = sigf(ov)*tanhf(c);
    cst[j] = c;
    hs[j] = h;
    g_Z[((size_t)b*ZC + 256 + dir*256 + j)*LSEQ + t] = h;
    __syncthreads();
  }
}

// ---------- ASPP branch: relu(conv3 dil d)+BN into g_Z chunk (f32x2 packed) ----------
__global__ void __launch_bounds__(256) aspp_kernel(
  const float* __restrict__ w, const float* __restrict__ bias,
  const float* __restrict__ bng, const float* __restrict__ bnb,
  int d, int outbase)
{
  const int t0 = blockIdx.x*64, c0 = blockIdx.y*64, b = blockIdx.z;
  __shared__ float xs[8][80];          // t range [t0-8, t0+71]
  __shared__ float ws2[24*66];         // [r = i*3+k][c], padded row 66
  const int tid = threadIdx.x, tt = tid & 15, tc = tid >> 4;
  u64 acc[2][4] = {};
  for (int cb = 0; cb < CC; cb += 8){
    __syncthreads();
    for (int idx = tid; idx < 8*80; idx += 256){
      int i = idx/80, jj = idx - i*80;
      int gx = t0 - 8 + jj;
      xs[i][jj] = (gx >= 0 && gx < LSEQ) ? g_Z[((size_t)b*ZC + cb+i)*LSEQ + gx] : 0.f;
    }
    for (int idx = tid; idx < 64*24; idx += 256){
      int cch = idx/24, r = idx - cch*24;   // r = i*3+k contiguous in global
      ws2[r*66 + cch] = w[((size_t)(c0+cch)*CC + cb)*3 + r];
    }
    __syncthreads();
    #pragma unroll
    for (int i = 0; i < 8; i++){
      u64 xb[3][4];
      #pragma unroll
      for (int jj = 0; jj < 4; jj++){
        int base = tt*4 + jj + 8;
        float v0 = xs[i][base-d], v1 = xs[i][base], v2 = xs[i][base+d];
        xb[0][jj] = pk2(v0, v0);
        xb[1][jj] = pk2(v1, v1);
        xb[2][jj] = pk2(v2, v2);
      }
      #pragma unroll
      for (int k = 0; k < 3; k++){
        const int rr = i*3 + k;
        u64 w0 = *(const u64*)(ws2 + rr*66 + tc*4);
        u64 w1 = *(const u64*)(ws2 + rr*66 + tc*4 + 2);
        #pragma unroll
        for (int jj = 0; jj < 4; jj++){
          fma2(acc[0][jj], xb[k][jj], w0);
          fma2(acc[1][jj], xb[k][jj], w1);
        }
      }
    }
  }
  const float inv = rsqrtf(1.f + 1e-5f);
  #pragma unroll
  for (int p = 0; p < 2; p++){
    int clo = c0 + tc*4 + 2*p, chi = clo + 1;
    float bglo = inv*bng[clo], bblo = bnb[clo], bilo = bias[clo];
    float bghi = inv*bng[chi], bbhi = bnb[chi], bihi = bias[chi];
    #pragma unroll
    for (int jj = 0; jj < 4; jj++){
      int t = t0 + tt*4 + jj;
      float2 v = up2(acc[p][jj]);
      float vlo = fmaxf(v.x + bilo, 0.f)*bglo + bblo;
      float vhi = fmaxf(v.y + bihi, 0.f)*bghi + bbhi;
      g_Z[((size_t)b*ZC + outbase + clo)*LSEQ + t] = vlo;
      g_Z[((size_t)b*ZC + outbase + chi)*LSEQ + t] = vhi;
    }
  }
}

// ---------- 1x1 head + log-sigmoid ----------
__global__ void __launch_bounds__(256) head_kernel(
  const float* __restrict__ w1, const float* __restrict__ b1, float* __restrict__ out)
{
  const int blk = blockIdx.x, b = blk >> 4, t0 = (blk & 15)*64;
  const int ct = threadIdx.x >> 6, tl = threadIdx.x & 63;
  const int t = t0 + tl;
  float acc[9] = {};
  const float* zp = g_Z + (size_t)b*ZC*LSEQ + t;
  for (int c = ct*960; c < ct*960 + 960; c++){
    float zv = zp[(size_t)c*LSEQ];
    #pragma unroll
    for (int cls = 0; cls < 9; cls++) acc[cls] = fmaf(zv, w1[cls*ZC + c], acc[cls]);
  }
  __shared__ float red[4][64][9];
  #pragma unroll
  for (int cls = 0; cls < 9; cls++) red[ct][tl][cls] = acc[cls];
  __syncthreads();
  if (ct == 0){
    #pragma unroll
    for (int cls = 0; cls < 9; cls++){
      float v = red[0][tl][cls] + red[1][tl][cls] + red[2][tl][cls] + red[3][tl][cls] + b1[cls];
      float ls = (v >= 0.f) ? -log1pf(expf(-v)) : (v - log1pf(expf(v)));
      out[((size_t)b*9 + cls)*LSEQ + t] = ls;
    }
  }
}

extern "C" void kernel_launch(void* const* d_in, const int* in_sizes, int n_in,
                              void* d_out, int out_size){
  const float* seq     = (const float*)d_in[0];
  const float* cond0_w = (const float*)d_in[1];
  const float* cond0_b = (const float*)d_in[2];
  const float* rout0_w = (const float*)d_in[3];
  const float* rout0_b = (const float*)d_in[4];
  const float* b0      = (const float*)d_in[5];
  const float* gate0_w = (const float*)d_in[6];
  const float* gate0_b = (const float*)d_in[7];
  const float* c0      = (const float*)d_in[8];
  const float* cond_ws = (const float*)d_in[9];
  const float* cond_bs = (const float*)d_in[10];
  const float* rout_ws = (const float*)d_in[11];
  const float* rout_bs = (const float*)d_in[12];
  const float* bs      = (const float*)d_in[13];
  const float* gate_ws = (const float*)d_in[14];
  const float* gate_bs = (const float*)d_in[15];
  const float* cs      = (const float*)d_in[16];
  const float* lstm_wih= (const float*)d_in[17];
  const float* lstm_whh= (const float*)d_in[18];
  const float* lstm_bih= (const float*)d_in[19];
  const float* lstm_bhh= (const float*)d_in[20];
  const float* aspp_ws = (const float*)d_in[21];
  const float* aspp_bs = (const float*)d_in[22];
  const float* bn_g    = (const float*)d_in[23];
  const float* bn_b    = (const float*)d_in[24];
  const float* conv1_w = (const float*)d_in[25];
  const float* conv1_b = (const float*)d_in[26];
  float* out = (float*)d_out;

  float *P0, *P1, *Z;
  cudaGetSymbolAddress((void**)&P0, g_P0);
  cudaGetSymbolAddress((void**)&P1, g_P1);
  cudaGetSymbolAddress((void**)&Z,  g_Z);

  const long PBS = (long)OO*LSEQ;
  const long ZBS = (long)ZC*LSEQ;
  dim3 gc(16, 4, 16);

  // biLSTM inputs first (independent of conv stack)
  dim3 gp(16, 16, 32);
  lstm_pregemm_kernel<<<gp, 256>>>(seq, lstm_wih, lstm_bih, lstm_bhh);
  whhT_kernel<<<2048, 256>>>(lstm_whh);
  lstm_step_kernel<<<32, 256>>>();

  // layer 0 (I = 128, input = seq)
  pool_kernel<<<BB*EE, 256>>>(seq);
  routing_kernel<<<1, 16>>>(rout0_w, rout0_b, EE);
  wbuild_kernel<<<(BB*((OO*EE*KK)/4) + 255)/256, 256>>>(cond0_w, EE);
  gated_conv_kernel<<<gc, 256>>>(seq, EE, (long)EE*LSEQ, P0, PBS, (const float*)0,
                                 gate0_w, cond0_b, b0, gate0_b, c0);

  // stacked layers (I = 256)
  const size_t WSTRIDE = (size_t)3*OO*OO*KK;
  const size_t GSTRIDE = (size_t)OO*OO*KK;
  const float* inb[4]  = { P0, P1, P0, P1 };
  float*       outb[4] = { P1, P0, P1, Z  };
  const float* resb[4] = { P0, 0,  P1, 0  };
  const long   obs[4]  = { PBS, PBS, PBS, ZBS };
  for (int i = 0; i < 4; i++){
    pool_kernel<<<BB*OO, 256>>>(inb[i]);
    routing_kernel<<<1, 16>>>(rout_ws + i*3*OO, rout_bs + i*3, OO);
    wbuild_kernel<<<(BB*((OO*OO*KK)/4) + 255)/256, 256>>>(cond_ws + i*WSTRIDE, OO);
    gated_conv_kernel<<<gc, 256>>>(inb[i], OO, PBS, outb[i], obs[i], resb[i],
                                   gate_ws + i*GSTRIDE, cond_bs + i*OO, bs + i*OO,
                                   gate_bs + i*OO, cs + i*OO);
  }

  // ASPP branches into g_Z chunks 1..4
  dim3 ga(16, 12, 16);
  const int dils[4] = {1, 2, 4, 8};
  for (int j = 0; j < 4; j++)
    aspp_kernel<<<ga, 256>>>(aspp_ws + (size_t)j*CC*CC*3, aspp_bs + j*CC,
                             bn_g + j*CC, bn_b + j*CC, dils[j], CC*(1+j));

  // head
  head_kernel<<<256, 256>>>(conv1_w, conv1_b, out);
}

// round 5
// speedup vs baseline: 2.1142x; 1.3856x over previous
#include <cuda_runtime.h>
#include <cuda_bf16.h>
#include <math.h>
#include <stdint.h>

#define BB 16
#define LSEQ 1024
#define EE 128
#define OO 256
#define HH 256
#define CC 768
#define ZC 3840
#define KK 11

typedef unsigned long long u64;

// ---------- static device scratch ----------
__device__ __align__(16) float g_P0[(size_t)BB*OO*LSEQ];
__device__ __align__(16) float g_P1[(size_t)BB*OO*LSEQ];
__device__ __align__(16) float g_Wb[(size_t)BB*OO*OO*KK];
__device__ float g_pooled[BB*OO];
__device__ float g_rbuf[BB*4];
__device__ __align__(16) float g_Z[(size_t)BB*ZC*LSEQ];     // [B,3840,L]
__device__ __align__(16) float g_G[(size_t)2*BB*LSEQ*1024]; // LSTM pre-gates
__device__ __align__(16) __nv_bfloat16 g_WTh[2*256*1024];   // Whh^T bf16: [dir][e][row]

__device__ __forceinline__ float sigf(float x){ return 1.f/(1.f+expf(-x)); }

__device__ __forceinline__ u64 pk2(float lo, float hi){
  u64 r; asm("mov.b64 %0, {%1, %2};" : "=l"(r) : "f"(lo), "f"(hi)); return r;
}
__device__ __forceinline__ void fma2(u64 &d, u64 a, u64 b){
  asm("fma.rn.f32x2 %0, %1, %2, %0;" : "+l"(d) : "l"(a), "l"(b));
}
__device__ __forceinline__ float2 up2(u64 v){
  float2 f; asm("mov.b64 {%0, %1}, %2;" : "=f"(f.x), "=f"(f.y) : "l"(v)); return f;
}

// ---------- row sums for routing pool ----------
__global__ void pool_kernel(const float* __restrict__ x){
  const float* row = x + (size_t)blockIdx.x * LSEQ;
  float s = 0.f;
  for (int t = threadIdx.x; t < LSEQ; t += 256) s += row[t];
  __shared__ float red[256];
  red[threadIdx.x] = s; __syncthreads();
  for (int off = 128; off; off >>= 1){
    if (threadIdx.x < off) red[threadIdx.x] += red[threadIdx.x+off];
    __syncthreads();
  }
  if (threadIdx.x == 0) g_pooled[blockIdx.x] = red[0];
}

// ---------- routing r = sigmoid(mean @ rw.T + rb) ----------
__global__ void routing_kernel(const float* __restrict__ rw, const float* __restrict__ rb, int I){
  int b = threadIdx.x;
  if (b >= BB) return;
  const float inv = 1.f / (float)(LSEQ + KK - 1);
  float rs = 0.f;
  for (int e = 0; e < 3; e++){
    float acc = rb[e];
    for (int i = 0; i < I; i++) acc = fmaf(g_pooled[b*I + i]*inv, rw[e*I+i], acc);
    float r = sigf(acc);
    g_rbuf[b*4+e] = r; rs += r;
  }
  g_rbuf[b*4+3] = rs;
}

// ---------- Wb[b] = sum_e r[b,e] * W[e] ----------
__global__ void wbuild_kernel(const float* __restrict__ W, int I){
  int per4 = (OO*I*KK) >> 2;
  int idx = blockIdx.x*256 + threadIdx.x;
  if (idx >= BB*per4) return;
  int b = idx / per4, m = idx - b*per4;
  const float4* w = (const float4*)W;
  float r0 = g_rbuf[b*4+0], r1 = g_rbuf[b*4+1], r2 = g_rbuf[b*4+2];
  float4 a = w[m], c = w[per4+m], d = w[2*per4+m];
  float4 o;
  o.x = r0*a.x + r1*c.x + r2*d.x;
  o.y = r0*a.y + r1*c.y + r2*d.y;
  o.z = r0*a.z + r1*c.z + r2*d.z;
  o.w = r0*a.w + r1*c.w + r2*d.w;
  ((float4*)g_Wb)[(size_t)b*per4 + m] = o;
}

// ---------- fused gated causal conv layer (f32x2 over output-channel pairs) ----------
__global__ void __launch_bounds__(256) gated_conv_kernel(
  const float* __restrict__ x, int I, long in_bs,
  float* __restrict__ out, long out_bs,
  const float* __restrict__ res,
  const float* __restrict__ Wg, const float* __restrict__ condb,
  const float* __restrict__ lbias, const float* __restrict__ gateb,
  const float* __restrict__ lc)
{
  const int t0 = blockIdx.x*64, o0 = blockIdx.y*64, b = blockIdx.z;
  __shared__ float xs[8][76];
  __shared__ float wa2[88*66];
  __shared__ float wg2[88*66];
  const int tid = threadIdx.x, tt = tid & 15, to = tid >> 4;
  u64 accA[2][4] = {}, accG[2][4] = {};
  const float* wbB = g_Wb + (size_t)b*OO*I*KK;

  for (int cb = 0; cb < I; cb += 8){
    __syncthreads();
    for (int idx = tid; idx < 8*74; idx += 256){
      int i = idx/74, j = idx - i*74;
      int tg = t0 - 10 + j;
      xs[i][j] = (tg >= 0) ? x[(size_t)b*in_bs + (size_t)(cb+i)*LSEQ + tg] : 0.f;
    }
    for (int idx = tid; idx < 88*64; idx += 256){
      int o = idx/88, r = idx - o*88;
      int gidx = ((o0+o)*I + cb)*KK + r;
      wa2[r*66 + o] = wbB[gidx];
      wg2[r*66 + o] = Wg[gidx];
    }
    __syncthreads();
    #pragma unroll
    for (int i = 0; i < 8; i++){
      u64 xb[14];
      #pragma unroll
      for (int m = 0; m < 14; m++){
        float xv = xs[i][tt*4 + m];
        xb[m] = pk2(xv, xv);
      }
      #pragma unroll
      for (int k = 0; k < 11; k++){
        const int rr = i*11 + k;
        u64 wA0 = *(const u64*)(wa2 + rr*66 + to*4);
        u64 wA1 = *(const u64*)(wa2 + rr*66 + to*4 + 2);
        u64 wG0 = *(const u64*)(wg2 + rr*66 + to*4);
        u64 wG1 = *(const u64*)(wg2 + rr*66 + to*4 + 2);
        #pragma unroll
        for (int jj = 0; jj < 4; jj++){
          fma2(accA[0][jj], xb[k+jj], wA0);
          fma2(accA[1][jj], xb[k+jj], wA1);
          fma2(accG[0][jj], xb[k+jj], wG0);
          fma2(accG[1][jj], xb[k+jj], wG1);
        }
      }
    }
  }
  float rsum = g_rbuf[b*4+3];
  #pragma unroll
  for (int p = 0; p < 2; p++){
    int olo = o0 + to*4 + 2*p, ohi = olo + 1;
    float cAlo = rsum*condb[olo] + lbias[olo], cAhi = rsum*condb[ohi] + lbias[ohi];
    float cGlo = gateb[olo] + lc[olo],         cGhi = gateb[ohi] + lc[ohi];
    #pragma unroll
    for (int jj = 0; jj < 4; jj++){
      int t = t0 + tt*4 + jj;
      float2 vA = up2(accA[p][jj]);
      float2 vG = up2(accG[p][jj]);
      float vlo = (vA.x + cAlo) * sigf(vG.x + cGlo);
      float vhi = (vA.y + cAhi) * sigf(vG.y + cGhi);
      if (res){
        vlo += res[(size_t)b*(OO*LSEQ) + (size_t)olo*LSEQ + t];
        vhi += res[(size_t)b*(OO*LSEQ) + (size_t)ohi*LSEQ + t];
      }
      out[(size_t)b*out_bs + (size_t)olo*LSEQ + t] = vlo;
      out[(size_t)b*out_bs + (size_t)ohi*LSEQ + t] = vhi;
    }
  }
}

// ---------- LSTM pre-gates ----------
__global__ void __launch_bounds__(256) lstm_pregemm_kernel(
  const float* __restrict__ seq, const float* __restrict__ wih,
  const float* __restrict__ bih, const float* __restrict__ bhh)
{
  const int t0 = blockIdx.x*64, g0 = blockIdx.y*64;
  const int blk = blockIdx.z, dir = blk >> 4, b = blk & 15;
  __shared__ float xs[16][64];
  __shared__ float ws[64][17];
  const int tid = threadIdx.x, tt = tid & 15, tg = tid >> 4;
  float acc[4][4] = {};
  const float* W = wih + (size_t)dir*1024*EE;
  for (int e0 = 0; e0 < EE; e0 += 16){
    __syncthreads();
    for (int idx = tid; idx < 16*64; idx += 256){
      int e = idx >> 6, t = idx & 63;
      xs[e][t] = seq[((size_t)b*EE + e0+e)*LSEQ + t0+t];
    }
    for (int idx = tid; idx < 64*16; idx += 256){
      int g = idx >> 4, e = idx & 15;
      ws[g][e] = W[(size_t)(g0+g)*EE + e0+e];
    }
    __syncthreads();
    #pragma unroll
    for (int e = 0; e < 16; e++){
      float wv[4];
      #pragma unroll
      for (int gj = 0; gj < 4; gj++) wv[gj] = ws[tt*4+gj][e];
      #pragma unroll
      for (int j = 0; j < 4; j++){
        float xv = xs[e][tg*4+j];
        #pragma unroll
        for (int gj = 0; gj < 4; gj++) acc[gj][j] = fmaf(xv, wv[gj], acc[gj][j]);
      }
    }
  }
  #pragma unroll
  for (int j = 0; j < 4; j++){
    int t = t0 + tg*4 + j;
    size_t base = (((size_t)blk << 10) + t) << 10;
    #pragma unroll
    for (int gj = 0; gj < 4; gj++){
      int g = g0 + tt*4 + gj;
      g_G[base + g] = acc[gj][j] + bih[dir*1024+g] + bhh[dir*1024+g];
    }
  }
}

// ---------- Whh^T -> bf16 [dir][e][row] ----------
__global__ void whhT_bf16_kernel(const float* __restrict__ whh){
  int idx = blockIdx.x*256 + threadIdx.x;      // 2*1024*256
  int dir = idx >> 18, rem = idx & 262143;
  int row = rem >> 8, e = rem & 255;
  g_WTh[dir*262144 + e*1024 + row] = __float2bfloat16(whh[idx]);
}

// ---------- sequential LSTM recurrence: bf16 weights, f32x2 accum ----------
// thread j owns gate-rows 4j..4j+3; per e: one LDG.64 (4 bf16) + decode + 2 FFMA2
__global__ void __launch_bounds__(256) lstm_step_kernel(){
  const int blk = blockIdx.x, dir = blk >> 4, b = blk & 15, j = threadIdx.x;
  __shared__ float gsm[1024];
  __shared__ u64 hs2[256];
  hs2[j] = 0ull;
  float cpriv = 0.f;
  const uint2* W2 = (const uint2*)(g_WTh + (size_t)dir*262144);
  __syncthreads();
  for (int s = 0; s < 1024; s++){
    int t = dir ? (1023 - s) : s;
    const float4* gp4 = (const float4*)(g_G + ((((size_t)blk << 10) + t) << 10));
    float4 av = gp4[j];
    u64 a01 = pk2(av.x, av.y), a23 = pk2(av.z, av.w);
    #pragma unroll 1
    for (int e0 = 0; e0 < 256; e0 += 16){
      uint2 w[16];
      #pragma unroll
      for (int q = 0; q < 16; q++) w[q] = W2[(e0+q)*256 + j];
      #pragma unroll
      for (int q = 0; q < 16; q++){
        u64 hb = hs2[e0+q];
        unsigned f0 = w[q].x << 16, f1 = w[q].x & 0xFFFF0000u;
        unsigned f2 = w[q].y << 16, f3 = w[q].y & 0xFFFF0000u;
        u64 w01 = pk2(__uint_as_float(f0), __uint_as_float(f1));
        u64 w23 = pk2(__uint_as_float(f2), __uint_as_float(f3));
        fma2(a01, hb, w01);
        fma2(a23, hb, w23);
      }
    }
    *(u64*)(gsm + 4*j)     = a01;
    *(u64*)(gsm + 4*j + 2) = a23;
    __syncthreads();
    float iv = gsm[j], fv = gsm[256+j], gv = gsm[512+j], ov = gsm[768+j];
    float c = sigf(fv)*cpriv + sigf(iv)*tanhf(gv);
    float h = sigf(ov)*tanhf(c);
    cpriv = c;
    hs2[j] = pk2(h, h);
    g_Z[((size_t)b*ZC + 256 + dir*256 + j)*LSEQ + t] = h;
    __syncthreads();
  }
}

// ---------- ASPP branch (f32x2) ----------
__global__ void __launch_bounds__(256) aspp_kernel(
  const float* __restrict__ w, const float* __restrict__ bias,
  const float* __restrict__ bng, const float* __restrict__ bnb,
  int d, int outbase)
{
  const int t0 = blockIdx.x*64, c0 = blockIdx.y*64, b = blockIdx.z;
  __shared__ float xs[8][80];
  __shared__ float ws2[24*66];
  const int tid = threadIdx.x, tt = tid & 15, tc = tid >> 4;
  u64 acc[2][4] = {};
  for (int cb = 0; cb < CC; cb += 8){
    __syncthreads();
    for (int idx = tid; idx < 8*80; idx += 256){
      int i = idx/80, jj = idx - i*80;
      int gx = t0 - 8 + jj;
      xs[i][jj] = (gx >= 0 && gx < LSEQ) ? g_Z[((size_t)b*ZC + cb+i)*LSEQ + gx] : 0.f;
    }
    for (int idx = tid; idx < 64*24; idx += 256){
      int cch = idx/24, r = idx - cch*24;
      ws2[r*66 + cch] = w[((size_t)(c0+cch)*CC + cb)*3 + r];
    }
    __syncthreads();
    #pragma unroll
    for (int i = 0; i < 8; i++){
      u64 xb[3][4];
      #pragma unroll
      for (int jj = 0; jj < 4; jj++){
        int base = tt*4 + jj + 8;
        float v0 = xs[i][base-d], v1 = xs[i][base], v2 = xs[i][base+d];
        xb[0][jj] = pk2(v0, v0);
        xb[1][jj] = pk2(v1, v1);
        xb[2][jj] = pk2(v2, v2);
      }
      #pragma unroll
      for (int k = 0; k < 3; k++){
        const int rr = i*3 + k;
        u64 w0 = *(const u64*)(ws2 + rr*66 + tc*4);
        u64 w1 = *(const u64*)(ws2 + rr*66 + tc*4 + 2);
        #pragma unroll
        for (int jj = 0; jj < 4; jj++){
          fma2(acc[0][jj], xb[k][jj], w0);
          fma2(acc[1][jj], xb[k][jj], w1);
        }
      }
    }
  }
  const float inv = rsqrtf(1.f + 1e-5f);
  #pragma unroll
  for (int p = 0; p < 2; p++){
    int clo = c0 + tc*4 + 2*p, chi = clo + 1;
    float bglo = inv*bng[clo], bblo = bnb[clo], bilo = bias[clo];
    float bghi = inv*bng[chi], bbhi = bnb[chi], bihi = bias[chi];
    #pragma unroll
    for (int jj = 0; jj < 4; jj++){
      int t = t0 + tt*4 + jj;
      float2 v = up2(acc[p][jj]);
      float vlo = fmaxf(v.x + bilo, 0.f)*bglo + bblo;
      float vhi = fmaxf(v.y + bihi, 0.f)*bghi + bbhi;
      g_Z[((size_t)b*ZC + outbase + clo)*LSEQ + t] = vlo;
      g_Z[((size_t)b*ZC + outbase + chi)*LSEQ + t] = vhi;
    }
  }
}

// ---------- 1x1 head + log-sigmoid ----------
__global__ void __launch_bounds__(256) head_kernel(
  const float* __restrict__ w1, const float* __restrict__ b1, float* __restrict__ out)
{
  const int blk = blockIdx.x, b = blk >> 4, t0 = (blk & 15)*64;
  const int ct = threadIdx.x >> 6, tl = threadIdx.x & 63;
  const int t = t0 + tl;
  float acc[9] = {};
  const float* zp = g_Z + (size_t)b*ZC*LSEQ + t;
  for (int c = ct*960; c < ct*960 + 960; c++){
    float zv = zp[(size_t)c*LSEQ];
    #pragma unroll
    for (int cls = 0; cls < 9; cls++) acc[cls] = fmaf(zv, w1[cls*ZC + c], acc[cls]);
  }
  __shared__ float red[4][64][9];
  #pragma unroll
  for (int cls = 0; cls < 9; cls++) red[ct][tl][cls] = acc[cls];
  __syncthreads();
  if (ct == 0){
    #pragma unroll
    for (int cls = 0; cls < 9; cls++){
      float v = red[0][tl][cls] + red[1][tl][cls] + red[2][tl][cls] + red[3][tl][cls] + b1[cls];
      float ls = (v >= 0.f) ? -log1pf(expf(-v)) : (v - log1pf(expf(v)));
      out[((size_t)b*9 + cls)*LSEQ + t] = ls;
    }
  }
}

extern "C" void kernel_launch(void* const* d_in, const int* in_sizes, int n_in,
                              void* d_out, int out_size){
  const float* seq     = (const float*)d_in[0];
  const float* cond0_w = (const float*)d_in[1];
  const float* cond0_b = (const float*)d_in[2];
  const float* rout0_w = (const float*)d_in[3];
  const float* rout0_b = (const float*)d_in[4];
  const float* b0      = (const float*)d_in[5];
  const float* gate0_w = (const float*)d_in[6];
  const float* gate0_b = (const float*)d_in[7];
  const float* c0      = (const float*)d_in[8];
  const float* cond_ws = (const float*)d_in[9];
  const float* cond_bs = (const float*)d_in[10];
  const float* rout_ws = (const float*)d_in[11];
  const float* rout_bs = (const float*)d_in[12];
  const float* bs      = (const float*)d_in[13];
  const float* gate_ws = (const float*)d_in[14];
  const float* gate_bs = (const float*)d_in[15];
  const float* cs      = (const float*)d_in[16];
  const float* lstm_wih= (const float*)d_in[17];
  const float* lstm_whh= (const float*)d_in[18];
  const float* lstm_bih= (const float*)d_in[19];
  const float* lstm_bhh= (const float*)d_in[20];
  const float* aspp_ws = (const float*)d_in[21];
  const float* aspp_bs = (const float*)d_in[22];
  const float* bn_g    = (const float*)d_in[23];
  const float* bn_b    = (const float*)d_in[24];
  const float* conv1_w = (const float*)d_in[25];
  const float* conv1_b = (const float*)d_in[26];
  float* out = (float*)d_out;

  float *P0, *P1, *Z;
  cudaGetSymbolAddress((void**)&P0, g_P0);
  cudaGetSymbolAddress((void**)&P1, g_P1);
  cudaGetSymbolAddress((void**)&Z,  g_Z);

  // side stream + events, created once on the eager correctness call
  static cudaStream_t s2 = 0;
  static cudaEvent_t evF = 0, evJ = 0;
  if (!s2){
    cudaStreamCreateWithFlags(&s2, cudaStreamNonBlocking);
    cudaEventCreateWithFlags(&evF, cudaEventDisableTiming);
    cudaEventCreateWithFlags(&evJ, cudaEventDisableTiming);
  }

  const long PBS = (long)OO*LSEQ;
  const long ZBS = (long)ZC*LSEQ;
  dim3 gc(16, 4, 16);

  // fork: LSTM branch on s2, conv stack on default stream
  cudaEventRecord(evF, 0);
  cudaStreamWaitEvent(s2, evF, 0);

  dim3 gp(16, 16, 32);
  lstm_pregemm_kernel<<<gp, 256, 0, s2>>>(seq, lstm_wih, lstm_bih, lstm_bhh);
  whhT_bf16_kernel<<<2048, 256, 0, s2>>>(lstm_whh);
  lstm_step_kernel<<<32, 256, 0, s2>>>();

  // conv stack: layer 0 (I = 128)
  pool_kernel<<<BB*EE, 256>>>(seq);
  routing_kernel<<<1, 16>>>(rout0_w, rout0_b, EE);
  wbuild_kernel<<<(BB*((OO*EE*KK)/4) + 255)/256, 256>>>(cond0_w, EE);
  gated_conv_kernel<<<gc, 256>>>(seq, EE, (long)EE*LSEQ, P0, PBS, (const float*)0,
                                 gate0_w, cond0_b, b0, gate0_b, c0);

  const size_t WSTRIDE = (size_t)3*OO*OO*KK;
  const size_t GSTRIDE = (size_t)OO*OO*KK;
  const float* inb[4]  = { P0, P1, P0, P1 };
  float*       outb[4] = { P1, P0, P1, Z  };
  const float* resb[4] = { P0, 0,  P1, 0  };
  const long   obs[4]  = { PBS, PBS, PBS, ZBS };
  for (int i = 0; i < 4; i++){
    pool_kernel<<<BB*OO, 256>>>(inb[i]);
    routing_kernel<<<1, 16>>>(rout_ws + i*3*OO, rout_bs + i*3, OO);
    wbuild_kernel<<<(BB*((OO*OO*KK)/4) + 255)/256, 256>>>(cond_ws + i*WSTRIDE, OO);
    gated_conv_kernel<<<gc, 256>>>(inb[i], OO, PBS, outb[i], obs[i], resb[i],
                                   gate_ws + i*GSTRIDE, cond_bs + i*OO, bs + i*OO,
                                   gate_bs + i*OO, cs + i*OO);
  }

  // join before ASPP (needs conv output channels 0..255 and lstm channels 256..767)
  cudaEventRecord(evJ, s2);
  cudaStreamWaitEvent(0, evJ, 0);

  dim3 ga(16, 12, 16);
  const int dils[4] = {1, 2, 4, 8};
  for (int j = 0; j < 4; j++)
    aspp_kernel<<<ga, 256>>>(aspp_ws + (size_t)j*CC*CC*3, aspp_bs + j*CC,
                             bn_g + j*CC, bn_b + j*CC, dils[j], CC*(1+j));

  head_kernel<<<256, 256>>>(conv1_w, conv1_b, out);
}

// round 6
// speedup vs baseline: 3.0307x; 1.4335x over previous
#include <cuda_runtime.h>
#include <cuda_bf16.h>
#include <math.h>
#include <stdint.h>

#define BB 16
#define LSEQ 1024
#define EE 128
#define OO 256
#define HH 256
#define CC 768
#define ZC 3840
#define KK 11

typedef unsigned long long u64;

// ---------- static device scratch ----------
__device__ __align__(16) float g_P0[(size_t)BB*OO*LSEQ];
__device__ __align__(16) float g_P1[(size_t)BB*OO*LSEQ];
__device__ __align__(16) float g_Wb[(size_t)BB*OO*OO*KK];
__device__ float g_pooled[BB*OO];
__device__ float g_rbuf[BB*4];
__device__ __align__(16) float g_Z[(size_t)BB*ZC*LSEQ];     // [B,3840,L]
__device__ __align__(16) float g_G[(size_t)2*BB*LSEQ*1024]; // LSTM pre-gates
__device__ __align__(16) unsigned g_Wpk[2*128*1024];        // Whh packed bf16x2: [dir][ep][row]

__device__ __forceinline__ float sigf(float x){ return 1.f/(1.f+expf(-x)); }

__device__ __forceinline__ u64 pk2(float lo, float hi){
  u64 r; asm("mov.b64 %0, {%1, %2};" : "=l"(r) : "f"(lo), "f"(hi)); return r;
}
__device__ __forceinline__ void fma2(u64 &d, u64 a, u64 b){
  asm("fma.rn.f32x2 %0, %1, %2, %0;" : "+l"(d) : "l"(a), "l"(b));
}
__device__ __forceinline__ float2 up2(u64 v){
  float2 f; asm("mov.b64 {%0, %1}, %2;" : "=f"(f.x), "=f"(f.y) : "l"(v)); return f;
}
__device__ __forceinline__ unsigned crank(){
  unsigned r; asm("mov.u32 %0, %%cluster_ctarank;" : "=r"(r)); return r;
}
__device__ __forceinline__ void cluster_sync_(){
  asm volatile("barrier.cluster.arrive.aligned;" ::: "memory");
  asm volatile("barrier.cluster.wait.aligned;" ::: "memory");
}
__device__ __forceinline__ unsigned s2u(const void* p){
  unsigned a; asm("{ .reg .u64 t; cvta.to.shared.u64 t, %1; cvt.u32.u64 %0, t; }" : "=r"(a) : "l"(p)); return a;
}
__device__ __forceinline__ float dsmem_ld(unsigned laddr, unsigned rk){
  unsigned ra; float v;
  asm volatile("mapa.shared::cluster.u32 %0, %1, %2;" : "=r"(ra) : "r"(laddr), "r"(rk));
  asm volatile("ld.shared::cluster.f32 %0, [%1];" : "=f"(v) : "r"(ra));
  return v;
}

// ---------- row sums for routing pool ----------
__global__ void pool_kernel(const float* __restrict__ x){
  const float* row = x + (size_t)blockIdx.x * LSEQ;
  float s = 0.f;
  for (int t = threadIdx.x; t < LSEQ; t += 256) s += row[t];
  __shared__ float red[256];
  red[threadIdx.x] = s; __syncthreads();
  for (int off = 128; off; off >>= 1){
    if (threadIdx.x < off) red[threadIdx.x] += red[threadIdx.x+off];
    __syncthreads();
  }
  if (threadIdx.x == 0) g_pooled[blockIdx.x] = red[0];
}

// ---------- routing r = sigmoid(mean @ rw.T + rb) ----------
__global__ void routing_kernel(const float* __restrict__ rw, const float* __restrict__ rb, int I){
  int b = threadIdx.x;
  if (b >= BB) return;
  const float inv = 1.f / (float)(LSEQ + KK - 1);
  float rs = 0.f;
  for (int e = 0; e < 3; e++){
    float acc = rb[e];
    for (int i = 0; i < I; i++) acc = fmaf(g_pooled[b*I + i]*inv, rw[e*I+i], acc);
    float r = sigf(acc);
    g_rbuf[b*4+e] = r; rs += r;
  }
  g_rbuf[b*4+3] = rs;
}

// ---------- Wb[b] = sum_e r[b,e] * W[e] ----------
__global__ void wbuild_kernel(const float* __restrict__ W, int I){
  int per4 = (OO*I*KK) >> 2;
  int idx = blockIdx.x*256 + threadIdx.x;
  if (idx >= BB*per4) return;
  int b = idx / per4, m = idx - b*per4;
  const float4* w = (const float4*)W;
  float r0 = g_rbuf[b*4+0], r1 = g_rbuf[b*4+1], r2 = g_rbuf[b*4+2];
  float4 a = w[m], c = w[per4+m], d = w[2*per4+m];
  float4 o;
  o.x = r0*a.x + r1*c.x + r2*d.x;
  o.y = r0*a.y + r1*c.y + r2*d.y;
  o.z = r0*a.z + r1*c.z + r2*d.z;
  o.w = r0*a.w + r1*c.w + r2*d.w;
  ((float4*)g_Wb)[(size_t)b*per4 + m] = o;
}

// ---------- fused gated causal conv layer (f32x2 over output-channel pairs) ----------
__global__ void __launch_bounds__(256) gated_conv_kernel(
  const float* __restrict__ x, int I, long in_bs,
  float* __restrict__ out, long out_bs,
  const float* __restrict__ res,
  const float* __restrict__ Wg, const float* __restrict__ condb,
  const float* __restrict__ lbias, const float* __restrict__ gateb,
  const float* __restrict__ lc)
{
  const int t0 = blockIdx.x*64, o0 = blockIdx.y*64, b = blockIdx.z;
  __shared__ float xs[8][76];
  __shared__ float wa2[88*66];
  __shared__ float wg2[88*66];
  const int tid = threadIdx.x, tt = tid & 15, to = tid >> 4;
  u64 accA[2][4] = {}, accG[2][4] = {};
  const float* wbB = g_Wb + (size_t)b*OO*I*KK;

  for (int cb = 0; cb < I; cb += 8){
    __syncthreads();
    for (int idx = tid; idx < 8*74; idx += 256){
      int i = idx/74, j = idx - i*74;
      int tg = t0 - 10 + j;
      xs[i][j] = (tg >= 0) ? x[(size_t)b*in_bs + (size_t)(cb+i)*LSEQ + tg] : 0.f;
    }
    for (int idx = tid; idx < 88*64; idx += 256){
      int o = idx/88, r = idx - o*88;
      int gidx = ((o0+o)*I + cb)*KK + r;
      wa2[r*66 + o] = wbB[gidx];
      wg2[r*66 + o] = Wg[gidx];
    }
    __syncthreads();
    #pragma unroll
    for (int i = 0; i < 8; i++){
      u64 xb[14];
      #pragma unroll
      for (int m = 0; m < 14; m++){
        float xv = xs[i][tt*4 + m];
        xb[m] = pk2(xv, xv);
      }
      #pragma unroll
      for (int k = 0; k < 11; k++){
        const int rr = i*11 + k;
        u64 wA0 = *(const u64*)(wa2 + rr*66 + to*4);
        u64 wA1 = *(const u64*)(wa2 + rr*66 + to*4 + 2);
        u64 wG0 = *(const u64*)(wg2 + rr*66 + to*4);
        u64 wG1 = *(const u64*)(wg2 + rr*66 + to*4 + 2);
        #pragma unroll
        for (int jj = 0; jj < 4; jj++){
          fma2(accA[0][jj], xb[k+jj], wA0);
          fma2(accA[1][jj], xb[k+jj], wA1);
          fma2(accG[0][jj], xb[k+jj], wG0);
          fma2(accG[1][jj], xb[k+jj], wG1);
        }
      }
    }
  }
  float rsum = g_rbuf[b*4+3];
  #pragma unroll
  for (int p = 0; p < 2; p++){
    int olo = o0 + to*4 + 2*p, ohi = olo + 1;
    float cAlo = rsum*condb[olo] + lbias[olo], cAhi = rsum*condb[ohi] + lbias[ohi];
    float cGlo = gateb[olo] + lc[olo],         cGhi = gateb[ohi] + lc[ohi];
    #pragma unroll
    for (int jj = 0; jj < 4; jj++){
      int t = t0 + tt*4 + jj;
      float2 vA = up2(accA[p][jj]);
      float2 vG = up2(accG[p][jj]);
      float vlo = (vA.x + cAlo) * sigf(vG.x + cGlo);
      float vhi = (vA.y + cAhi) * sigf(vG.y + cGhi);
      if (res){
        vlo += res[(size_t)b*(OO*LSEQ) + (size_t)olo*LSEQ + t];
        vhi += res[(size_t)b*(OO*LSEQ) + (size_t)ohi*LSEQ + t];
      }
      out[(size_t)b*out_bs + (size_t)olo*LSEQ + t] = vlo;
      out[(size_t)b*out_bs + (size_t)ohi*LSEQ + t] = vhi;
    }
  }
}

// ---------- LSTM pre-gates ----------
__global__ void __launch_bounds__(256) lstm_pregemm_kernel(
  const float* __restrict__ seq, const float* __restrict__ wih,
  const float* __restrict__ bih, const float* __restrict__ bhh)
{
  const int t0 = blockIdx.x*64, g0 = blockIdx.y*64;
  const int blk = blockIdx.z, dir = blk >> 4, b = blk & 15;
  __shared__ float xs[16][64];
  __shared__ float ws[64][17];
  const int tid = threadIdx.x, tt = tid & 15, tg = tid >> 4;
  float acc[4][4] = {};
  const float* W = wih + (size_t)dir*1024*EE;
  for (int e0 = 0; e0 < EE; e0 += 16){
    __syncthreads();
    for (int idx = tid; idx < 16*64; idx += 256){
      int e = idx >> 6, t = idx & 63;
      xs[e][t] = seq[((size_t)b*EE + e0+e)*LSEQ + t0+t];
    }
    for (int idx = tid; idx < 64*16; idx += 256){
      int g = idx >> 4, e = idx & 15;
      ws[g][e] = W[(size_t)(g0+g)*EE + e0+e];
    }
    __syncthreads();
    #pragma unroll
    for (int e = 0; e < 16; e++){
      float wv[4];
      #pragma unroll
      for (int gj = 0; gj < 4; gj++) wv[gj] = ws[tt*4+gj][e];
      #pragma unroll
      for (int j = 0; j < 4; j++){
        float xv = xs[e][tg*4+j];
        #pragma unroll
        for (int gj = 0; gj < 4; gj++) acc[gj][j] = fmaf(xv, wv[gj], acc[gj][j]);
      }
    }
  }
  #pragma unroll
  for (int j = 0; j < 4; j++){
    int t = t0 + tg*4 + j;
    size_t base = (((size_t)blk << 10) + t) << 10;
    #pragma unroll
    for (int gj = 0; gj < 4; gj++){
      int g = g0 + tt*4 + gj;
      g_G[base + g] = acc[gj][j] + bih[dir*1024+g] + bhh[dir*1024+g];
    }
  }
}

// ---------- Whh -> packed bf16x2 [dir][ep][row] ----------
__global__ void wpk_kernel(const float* __restrict__ whh){
  int idx = blockIdx.x*256 + threadIdx.x;   // 2*128*1024 = 262144
  if (idx >= 262144) return;
  int dir = idx >> 17, rem = idx & 131071, ep = rem >> 10, row = rem & 1023;
  const float* wsrc = whh + (size_t)dir*262144 + (size_t)row*256 + 2*ep;
  unsigned p;
  asm("cvt.rn.bf16x2.f32 %0, %1, %2;" : "=r"(p) : "f"(wsrc[1]), "f"(wsrc[0]));
  g_Wpk[idx] = p;
}

// ---------- cluster-resident LSTM recurrence ----------
// One chain (dir,b) = cluster of 4 CTAs. CTA rank k owns gate type k (256 rows),
// weights in SMEM (128KB bf16), h replicated per CTA, gate exchange via DSMEM.
#define SM_WS   0
#define SM_HBUF 131072
#define SM_GST  (131072 + 1024)
#define SM_HIST (131072 + 1024 + 2048)
#define SM_LSTM (SM_HIST + 32*257*4)   // 167,040 B

__global__ void __launch_bounds__(256,1) __cluster_dims__(4,1,1)
lstm_cluster_kernel(){
  extern __shared__ char smraw[];
  uint32_t* WS = (uint32_t*)(smraw + SM_WS);     // [128][256] bf16x2
  float* hbuf  = (float*)(smraw + SM_HBUF);      // [256]
  float* gst   = (float*)(smraw + SM_GST);       // [2][256]
  float* hist  = (float*)(smraw + SM_HIST);      // [32][257]
  const int j = threadIdx.x;
  const unsigned rk = crank();
  const int chain = blockIdx.x >> 2, dir = chain >> 4, b = chain & 15;

  // load this CTA's weight slab: WS[ep][r] = g_Wpk[dir][ep][rk*256 + r]
  {
    uint4* dst = (uint4*)WS;
    for (int m = j; m < 128*64; m += 256){
      int ep = m >> 6, r4 = m & 63;
      dst[m] = *(const uint4*)(g_Wpk + (size_t)dir*131072 + ep*1024 + rk*256 + r4*4);
    }
  }
  hbuf[j] = 0.f;
  float cstate = 0.f;
  __syncthreads();

  const float* gpre = g_G + ((size_t)chain << 20) + rk*256 + j;
  const unsigned gstL = s2u(gst) + 4*j;

  for (int s = 0; s < 1024; s++){
    const int t = dir ? (1023 - s) : s;
    float pre = gpre[(size_t)t << 10];         // early LDG, consumed after loop
    u64 acc = pk2(0.f, 0.f);
    #pragma unroll 8
    for (int ep = 0; ep < 128; ep++){
      uint32_t w = WS[(ep<<8) + j];
      u64 hp = *(const u64*)(hbuf + 2*ep);
      unsigned wlo = w << 16, whi = w & 0xFFFF0000u;
      u64 wp = pk2(__uint_as_float(wlo), __uint_as_float(whi));
      fma2(acc, hp, wp);
    }
    float2 v = up2(acc);
    const int slot = s & 1;
    gst[slot*256 + j] = v.x + v.y + pre;
    cluster_sync_();
    const unsigned base = gstL + slot*1024;
    float iv = dsmem_ld(base, 0);
    float fv = dsmem_ld(base, 1);
    float gv = dsmem_ld(base, 2);
    float ov = dsmem_ld(base, 3);
    cstate = sigf(fv)*cstate + sigf(iv)*tanhf(gv);
    float h = sigf(ov)*tanhf(cstate);
    hbuf[j] = h;
    hist[(t & 31)*257 + j] = h;
    __syncthreads();
    if ((s & 31) == 31){
      if (j < 64){
        int c = rk*64 + j;
        int tb = t & ~31;
        float* dstz = g_Z + ((size_t)b*ZC + 256 + dir*256 + c)*LSEQ + tb;
        #pragma unroll
        for (int m4 = 0; m4 < 8; m4++){
          float4 vv;
          vv.x = hist[(m4*4+0)*257 + c];
          vv.y = hist[(m4*4+1)*257 + c];
          vv.z = hist[(m4*4+2)*257 + c];
          vv.w = hist[(m4*4+3)*257 + c];
          *(float4*)(dstz + m4*4) = vv;
        }
      }
      __syncthreads();
    }
  }
}

// ---------- ASPP branch (f32x2) ----------
__global__ void __launch_bounds__(256) aspp_kernel(
  const float* __restrict__ w, const float* __restrict__ bias,
  const float* __restrict__ bng, const float* __restrict__ bnb,
  int d, int outbase)
{
  const int t0 = blockIdx.x*64, c0 = blockIdx.y*64, b = blockIdx.z;
  __shared__ float xs[8][80];
  __shared__ float ws2[24*66];
  const int tid = threadIdx.x, tt = tid & 15, tc = tid >> 4;
  u64 acc[2][4] = {};
  for (int cb = 0; cb < CC; cb += 8){
    __syncthreads();
    for (int idx = tid; idx < 8*80; idx += 256){
      int i = idx/80, jj = idx - i*80;
      int gx = t0 - 8 + jj;
      xs[i][jj] = (gx >= 0 && gx < LSEQ) ? g_Z[((size_t)b*ZC + cb+i)*LSEQ + gx] : 0.f;
    }
    for (int idx = tid; idx < 64*24; idx += 256){
      int cch = idx/24, r = idx - cch*24;
      ws2[r*66 + cch] = w[((size_t)(c0+cch)*CC + cb)*3 + r];
    }
    __syncthreads();
    #pragma unroll
    for (int i = 0; i < 8; i++){
      u64 xb[3][4];
      #pragma unroll
      for (int jj = 0; jj < 4; jj++){
        int base = tt*4 + jj + 8;
        float v0 = xs[i][base-d], v1 = xs[i][base], v2 = xs[i][base+d];
        xb[0][jj] = pk2(v0, v0);
        xb[1][jj] = pk2(v1, v1);
        xb[2][jj] = pk2(v2, v2);
      }
      #pragma unroll
      for (int k = 0; k < 3; k++){
        const int rr = i*3 + k;
        u64 w0 = *(const u64*)(ws2 + rr*66 + tc*4);
        u64 w1 = *(const u64*)(ws2 + rr*66 + tc*4 + 2);
        #pragma unroll
        for (int jj = 0; jj < 4; jj++){
          fma2(acc[0][jj], xb[k][jj], w0);
          fma2(acc[1][jj], xb[k][jj], w1);
        }
      }
    }
  }
  const float inv = rsqrtf(1.f + 1e-5f);
  #pragma unroll
  for (int p = 0; p < 2; p++){
    int clo = c0 + tc*4 + 2*p, chi = clo + 1;
    float bglo = inv*bng[clo], bblo = bnb[clo], bilo = bias[clo];
    float bghi = inv*bng[chi], bbhi = bnb[chi], bihi = bias[chi];
    #pragma unroll
    for (int jj = 0; jj < 4; jj++){
      int t = t0 + tt*4 + jj;
      float2 v = up2(acc[p][jj]);
      float vlo = fmaxf(v.x + bilo, 0.f)*bglo + bblo;
      float vhi = fmaxf(v.y + bihi, 0.f)*bghi + bbhi;
      g_Z[((size_t)b*ZC + outbase + clo)*LSEQ + t] = vlo;
      g_Z[((size_t)b*ZC + outbase + chi)*LSEQ + t] = vhi;
    }
  }
}

// ---------- 1x1 head + log-sigmoid ----------
__global__ void __launch_bounds__(256) head_kernel(
  const float* __restrict__ w1, const float* __restrict__ b1, float* __restrict__ out)
{
  const int blk = blockIdx.x, b = blk >> 4, t0 = (blk & 15)*64;
  const int ct = threadIdx.x >> 6, tl = threadIdx.x & 63;
  const int t = t0 + tl;
  float acc[9] = {};
  const float* zp = g_Z + (size_t)b*ZC*LSEQ + t;
  for (int c = ct*960; c < ct*960 + 960; c++){
    float zv = zp[(size_t)c*LSEQ];
    #pragma unroll
    for (int cls = 0; cls < 9; cls++) acc[cls] = fmaf(zv, w1[cls*ZC + c], acc[cls]);
  }
  __shared__ float red[4][64][9];
  #pragma unroll
  for (int cls = 0; cls < 9; cls++) red[ct][tl][cls] = acc[cls];
  __syncthreads();
  if (ct == 0){
    #pragma unroll
    for (int cls = 0; cls < 9; cls++){
      float v = red[0][tl][cls] + red[1][tl][cls] + red[2][tl][cls] + red[3][tl][cls] + b1[cls];
      float ls = (v >= 0.f) ? -log1pf(expf(-v)) : (v - log1pf(expf(v)));
      out[((size_t)b*9 + cls)*LSEQ + t] = ls;
    }
  }
}

extern "C" void kernel_launch(void* const* d_in, const int* in_sizes, int n_in,
                              void* d_out, int out_size){
  const float* seq     = (const float*)d_in[0];
  const float* cond0_w = (const float*)d_in[1];
  const float* cond0_b = (const float*)d_in[2];
  const float* rout0_w = (const float*)d_in[3];
  const float* rout0_b = (const float*)d_in[4];
  const float* b0      = (const float*)d_in[5];
  const float* gate0_w = (const float*)d_in[6];
  const float* gate0_b = (const float*)d_in[7];
  const float* c0      = (const float*)d_in[8];
  const float* cond_ws = (const float*)d_in[9];
  const float* cond_bs = (const float*)d_in[10];
  const float* rout_ws = (const float*)d_in[11];
  const float* rout_bs = (const float*)d_in[12];
  const float* bs      = (const float*)d_in[13];
  const float* gate_ws = (const float*)d_in[14];
  const float* gate_bs = (const float*)d_in[15];
  const float* cs      = (const float*)d_in[16];
  const float* lstm_wih= (const float*)d_in[17];
  const float* lstm_whh= (const float*)d_in[18];
  const float* lstm_bih= (const float*)d_in[19];
  const float* lstm_bhh= (const float*)d_in[20];
  const float* aspp_ws = (const float*)d_in[21];
  const float* aspp_bs = (const float*)d_in[22];
  const float* bn_g    = (const float*)d_in[23];
  const float* bn_b    = (const float*)d_in[24];
  const float* conv1_w = (const float*)d_in[25];
  const float* conv1_b = (const float*)d_in[26];
  float* out = (float*)d_out;

  float *P0, *P1, *Z;
  cudaGetSymbolAddress((void**)&P0, g_P0);
  cudaGetSymbolAddress((void**)&P1, g_P1);
  cudaGetSymbolAddress((void**)&Z,  g_Z);

  static cudaStream_t s2 = 0;
  static cudaEvent_t evF = 0, evJ = 0;
  if (!s2){
    cudaStreamCreateWithFlags(&s2, cudaStreamNonBlocking);
    cudaEventCreateWithFlags(&evF, cudaEventDisableTiming);
    cudaEventCreateWithFlags(&evJ, cudaEventDisableTiming);
    cudaFuncSetAttribute(lstm_cluster_kernel,
                         cudaFuncAttributeMaxDynamicSharedMemorySize, SM_LSTM);
  }

  const long PBS = (long)OO*LSEQ;
  const long ZBS = (long)ZC*LSEQ;
  dim3 gc(16, 4, 16);

  // fork: LSTM branch on s2, conv stack on default stream
  cudaEventRecord(evF, 0);
  cudaStreamWaitEvent(s2, evF, 0);

  dim3 gp(16, 16, 32);
  lstm_pregemm_kernel<<<gp, 256, 0, s2>>>(seq, lstm_wih, lstm_bih, lstm_bhh);
  wpk_kernel<<<1024, 256, 0, s2>>>(lstm_whh);
  lstm_cluster_kernel<<<128, 256, SM_LSTM, s2>>>();

  // conv stack: layer 0 (I = 128)
  pool_kernel<<<BB*EE, 256>>>(seq);
  routing_kernel<<<1, 16>>>(rout0_w, rout0_b, EE);
  wbuild_kernel<<<(BB*((OO*EE*KK)/4) + 255)/256, 256>>>(cond0_w, EE);
  gated_conv_kernel<<<gc, 256>>>(seq, EE, (long)EE*LSEQ, P0, PBS, (const float*)0,
                                 gate0_w, cond0_b, b0, gate0_b, c0);

  const size_t WSTRIDE = (size_t)3*OO*OO*KK;
  const size_t GSTRIDE = (size_t)OO*OO*KK;
  const float* inb[4]  = { P0, P1, P0, P1 };
  float*       outb[4] = { P1, P0, P1, Z  };
  const float* resb[4] = { P0, 0,  P1, 0  };
  const long   obs[4]  = { PBS, PBS, PBS, ZBS };
  for (int i = 0; i < 4; i++){
    pool_kernel<<<BB*OO, 256>>>(inb[i]);
    routing_kernel<<<1, 16>>>(rout_ws + i*3*OO, rout_bs + i*3, OO);
    wbuild_kernel<<<(BB*((OO*OO*KK)/4) + 255)/256, 256>>>(cond_ws + i*WSTRIDE, OO);
    gated_conv_kernel<<<gc, 256>>>(inb[i], OO, PBS, outb[i], obs[i], resb[i],
                                   gate_ws + i*GSTRIDE, cond_bs + i*OO, bs + i*OO,
                                   gate_bs + i*OO, cs + i*OO);
  }

  // join before ASPP
  cudaEventRecord(evJ, s2);
  cudaStreamWaitEvent(0, evJ, 0);

  dim3 ga(16, 12, 16);
  const int dils[4] = {1, 2, 4, 8};
  for (int j = 0; j < 4; j++)
    aspp_kernel<<<ga, 256>>>(aspp_ws + (size_t)j*CC*CC*3, aspp_bs + j*CC,
                             bn_g + j*CC, bn_b + j*CC, dils[j], CC*(1+j));

  head_kernel<<<256, 256>>>(conv1_w, conv1_b, out);
}